// round 9
// baseline (speedup 1.0000x reference)
#include <cuda_runtime.h>
#include <cuda_fp16.h>
#include <math.h>
#include <stdint.h>

// Problem constants
#define BB   256
#define TT   512
#define DIN  64
#define HH   1024
#define DOUT 10

// Config: 128 CTAs (4 batch-tiles x 32 h-tiles), tile 64 batch x 32 h-out
#define GRID 128
#define NTH  256
#define BT   64
#define HT   32
#define KCH  64
#define NCH  17            // 16 h-chunks + 1 x-chunk

// SMEM layout (bytes). Strides padded so 8-row ldmatrix groups hit distinct banks.
#define BSTRIDE_H 1096                     // halves per Whh row (1024 + 64 Whx + 8 pad)
#define BSTRIDE_B (BSTRIDE_H*2)            // 2192 B = 548 words == 4 mod 32
#define ASTRIDE_H 72                       // halves per A row (64 + 8 pad)
#define ASTRIDE_B (ASTRIDE_H*2)            // 144 B
#define ABUF_B    (BT*ASTRIDE_B)           // 9216 B per chunk buffer
#define SM_B      0
#define SM_B_SZ   (HT*BSTRIDE_B)           // 70144
#define SM_A      SM_B_SZ
#define SM_A_SZ   (NCH*ABUF_B)             // 156672
#define SM_BIAS   (SM_A + SM_A_SZ)         // 226816
#define SMEM_BYTES (SM_BIAS + 128)         // 226944  (< 232448 cap)

#define SPIN_BOUND (1u<<17)   // wall-clock-bounded; latch makes failure a one-time cost

// Global scratch (__device__ globals: allocation-free rule)
__device__ __align__(256) __half g_h[2][BB][HH];       // double-buffered hidden state fp16
__device__ __align__(256) __half g_x[TT][BB][DIN];     // x pre-converted fp16, [t][b][d]
__device__ __align__(256) unsigned g_arrive[TT][GRID]; // per-CTA arrival flags
__device__ unsigned g_go[TT];                          // per-step release flags

// ---------------- helpers ----------------
__device__ __forceinline__ void cp_async16(void* sptr, const void* gptr) {
    uint32_t s = (uint32_t)__cvta_generic_to_shared(sptr);
    asm volatile("cp.async.cg.shared.global [%0], [%1], 16;" :: "r"(s), "l"(gptr));
}
__device__ __forceinline__ void cp_commit() { asm volatile("cp.async.commit_group;"); }
template<int N> __device__ __forceinline__ void cp_wait() {
    asm volatile("cp.async.wait_group %0;" :: "n"(N));
}
// switch folds to the right immediate under full unroll
__device__ __forceinline__ void cp_wait_dyn(int n) {
    switch (n) {
    case 0:  cp_wait<0>();  break;  case 1:  cp_wait<1>();  break;
    case 2:  cp_wait<2>();  break;  case 3:  cp_wait<3>();  break;
    case 4:  cp_wait<4>();  break;  case 5:  cp_wait<5>();  break;
    case 6:  cp_wait<6>();  break;  case 7:  cp_wait<7>();  break;
    case 8:  cp_wait<8>();  break;  case 9:  cp_wait<9>();  break;
    case 10: cp_wait<10>(); break;  case 11: cp_wait<11>(); break;
    case 12: cp_wait<12>(); break;  case 13: cp_wait<13>(); break;
    case 14: cp_wait<14>(); break;  case 15: cp_wait<15>(); break;
    default: cp_wait<16>(); break;
    }
}

__device__ __forceinline__ void ldsm_x4(uint32_t& r0, uint32_t& r1, uint32_t& r2, uint32_t& r3,
                                        uint32_t addr) {
    asm volatile("ldmatrix.sync.aligned.m8n8.x4.shared.b16 {%0,%1,%2,%3}, [%4];"
                 : "=r"(r0), "=r"(r1), "=r"(r2), "=r"(r3) : "r"(addr));
}

__device__ __forceinline__ void mma16816(float* c, const uint32_t* a, uint32_t b0, uint32_t b1) {
    asm volatile(
        "mma.sync.aligned.m16n8k16.row.col.f32.f16.f16.f32 "
        "{%0,%1,%2,%3}, {%4,%5,%6,%7}, {%8,%9}, {%0,%1,%2,%3};"
        : "+f"(c[0]), "+f"(c[1]), "+f"(c[2]), "+f"(c[3])
        : "r"(a[0]), "r"(a[1]), "r"(a[2]), "r"(a[3]), "r"(b0), "r"(b1));
}

__device__ __forceinline__ float tanh_fast(float x) {
    float e = __expf(2.0f * x);
    return 1.0f - __fdividef(2.0f, e + 1.0f);
}

// ---------------- init: zero state, convert x fp32->fp16 into [t][b][d] ----------------
__global__ void rnn_init_kernel(const float* __restrict__ x) {
    int i = blockIdx.x * blockDim.x + threadIdx.x;
    int stride = gridDim.x * blockDim.x;
    if (i < BB*HH) ((__half*)g_h)[i] = __ushort_as_half((unsigned short)0);
    if (i < TT) g_go[i] = 0u;
    for (int j = i; j < TT*GRID; j += stride) ((unsigned*)g_arrive)[j] = 0u;
    for (int j = i; j < BB*TT*DIN; j += stride) {
        int d = j & 63;
        int t = (j >> 6) & 511;
        int b = j >> 15;
        g_x[t][b][d] = __float2half_rn(x[j]);
    }
}

// ---------------- persistent RNN kernel ----------------
__global__ void __launch_bounds__(NTH, 1)
rnn_hmma_kernel(const float* __restrict__ Whh, const float* __restrict__ Whx,
                const float* __restrict__ bh,  const float* __restrict__ Why,
                const float* __restrict__ by,  float* __restrict__ out)
{
    extern __shared__ char sm[];
    const uint32_t smb = (uint32_t)__cvta_generic_to_shared(sm);
    const int tid = threadIdx.x, warp = tid >> 5, lane = tid & 31;
    const int cta = blockIdx.x;
    const int jb = cta & 31, ib = cta >> 5;    // 32 h-tiles x 4 b-tiles
    const int h_base = jb * HT;
    const int b_base = ib * BT;

    // ---- stage B once: Whh [32,1024] + Whx [32,64] as fp16 rows of stride 1096 ----
    __half* bs = (__half*)(sm + SM_B);
    for (int i = tid; i < HT*HH/2; i += NTH) {
        int n = i >> 9, k = (i & 511) * 2;
        const float* src = &Whh[(size_t)(h_base + n)*HH + k];
        *(__half2*)&bs[n*BSTRIDE_H + k] = __floats2half2_rn(src[0], src[1]);
    }
    for (int i = tid; i < HT*DIN/2; i += NTH) {
        int n = i >> 5, k = (i & 31) * 2;
        *(__half2*)&bs[n*BSTRIDE_H + 1024 + k] =
            __floats2half2_rn(Whx[(h_base + n)*DIN + k], Whx[(h_base + n)*DIN + k + 1]);
    }
    float* bias_s = (float*)(sm + SM_BIAS);
    if (tid < HT) bias_s[tid] = bh[h_base + tid];
    __syncthreads();

    // warp tiling: 4 m-warps (16 rows each) x 2 n-warps (16 cols each)
    const int wp   = warp >> 1;       // pair id 0..3 (m-tile)
    const int wm   = wp * 16;
    const int wn   = (warp & 1) * 16;
    const int grp  = lane >> 2, thr4 = lane & 3;
    const int ptid = tid & 63;        // thread id within the 64-thread pair

    // ldmatrix lane address components
    const int a_row  = wm + (lane & 7) + 8*((lane >> 3) & 1);
    const int a_koff = 8 * (lane >> 4);
    const int b_row  = wn + (lane & 7) + 8*(lane >> 4);
    const int b_koff = 8 * ((lane >> 3) & 1);
    const uint32_t a_lane = smb + SM_A + a_row*ASTRIDE_B + a_koff*2;
    const uint32_t b_lane = smb + SM_B + b_row*BSTRIDE_B + b_koff*2;

    bool alive = true;

    for (int t = 0; t < TT; ++t) {
        const __half* hsrc = &g_h[t & 1][0][0];

        // ---- stage ALL 17 chunks up-front: each pair stages its own 16 A rows ----
        {
            const int r = wm + (ptid >> 3);       // row handled (2 rows per thread: +8)
            const int q = ptid & 7;               // 16B piece within chunk row
            #pragma unroll
            for (int c = 0; c < NCH; ++c) {
                char* dst0 = sm + SM_A + c*ABUF_B + r*ASTRIDE_B + q*16;
                if (c < 16) {
                    const __half* s0 = hsrc + (size_t)(b_base + r)*HH + c*KCH + q*8;
                    cp_async16(dst0,                  s0);
                    cp_async16(dst0 + 8*ASTRIDE_B,    s0 + 8*HH);
                } else {
                    const __half* s0 = &g_x[t][b_base + r][q*8];
                    cp_async16(dst0,                  s0);
                    cp_async16(dst0 + 8*ASTRIDE_B,    s0 + 8*DIN);
                }
                cp_commit();
            }
        }

        float acc0[4] = {0.f,0.f,0.f,0.f};
        float acc1[4] = {0.f,0.f,0.f,0.f};

        // ---- compute: consume chunks as they land; pair-local sync only ----
        #pragma unroll
        for (int c = 0; c < NCH; ++c) {
            cp_wait_dyn(16 - c);                       // own groups <= c complete
            asm volatile("bar.sync %0, 64;" :: "r"(wp + 1) : "memory");  // pair staged

            const uint32_t abase = a_lane + c * ABUF_B;
            const uint32_t bbase = b_lane + c * (KCH * 2);
            #pragma unroll
            for (int kk = 0; kk < 4; ++kk) {
                uint32_t a0,a1,a2,a3, b0,b1,b2,b3;
                ldsm_x4(a0,a1,a2,a3, abase + kk*32);
                ldsm_x4(b0,b1,b2,b3, bbase + kk*32);
                uint32_t a[4] = {a0,a1,a2,a3};
                mma16816(acc0, a, b0, b1);
                mma16816(acc1, a, b2, b3);
            }
        }

        // ---- epilogue: bias + tanh, store h_new fp16 (per-warp independent) ----
        {
            __half* hdst = &g_h[(t + 1) & 1][0][0];
            const int r0 = b_base + wm + grp;
            #pragma unroll
            for (int tile = 0; tile < 2; ++tile) {
                const float* a = tile ? acc1 : acc0;
                const int col = h_base + wn + tile*8 + 2*thr4;
                float bl  = bias_s[wn + tile*8 + 2*thr4];
                float bhp = bias_s[wn + tile*8 + 2*thr4 + 1];
                __half2 v0 = __floats2half2_rn(tanh_fast(a[0] + bl), tanh_fast(a[1] + bhp));
                __half2 v1 = __floats2half2_rn(tanh_fast(a[2] + bl), tanh_fast(a[3] + bhp));
                *(__half2*)&hdst[(size_t)r0*HH + col]     = v0;
                *(__half2*)&hdst[(size_t)(r0+8)*HH + col] = v1;
            }
        }

        // ---- grid barrier: flag arrival + CTA0 aggregation + go broadcast ----
        __threadfence();
        __syncthreads();
        if (tid == 0) {
            asm volatile("st.release.gpu.global.u32 [%0], %1;"
                         :: "l"(&g_arrive[t][cta]), "r"(1u) : "memory");
        }
        if (cta == 0 && warp == 0) {
            // warp 0 of CTA 0 aggregates 128 flags (4 per lane)
            bool ok = false;
            if (alive) {
                for (unsigned it = 0; it < SPIN_BOUND; ++it) {
                    unsigned f0,f1,f2,f3;
                    asm volatile("ld.global.cg.v4.u32 {%0,%1,%2,%3}, [%4];"
                                 : "=r"(f0),"=r"(f1),"=r"(f2),"=r"(f3)
                                 : "l"(&g_arrive[t][lane*4]) : "memory");
                    if (__all_sync(0xffffffffu, (f0 & f1 & f2 & f3) == 1u)) { ok = true; break; }
                }
                if (!ok) alive = false;
            }
            if (lane == 0) {
                __threadfence();
                asm volatile("st.release.gpu.global.u32 [%0], %1;"
                             :: "l"(&g_go[t]), "r"(1u) : "memory");
            }
        }
        if (tid == 0) {
            if (alive) {
                unsigned it = 0, go = 0;
                do {
                    asm volatile("ld.acquire.gpu.global.u32 %0, [%1];"
                                 : "=r"(go) : "l"(&g_go[t]) : "memory");
                } while (go == 0u && ++it < SPIN_BOUND);
                if (go == 0u) alive = false;
            }
            __threadfence();
        }
        __syncthreads();
    }

    // ---- output: o = h_final @ Why^T + by, softmax over 10 (2 batch rows per CTA) ----
    float* logits = (float*)(sm + SM_A);   // 20 floats; mainloop smem dead now
    const __half* hf = &g_h[0][0][0];      // TT even -> final h in buffer 0
    for (int d = warp; d < 2*DOUT; d += 8) {
        int row = d / DOUT, col = d % DOUT;
        int b = 2*cta + row;
        const __half* hp = hf + (size_t)b*HH;
        const float* wpw = Why + (size_t)col*HH;
        float s = 0.f;
        for (int k = lane; k < HH; k += 32)
            s += __half2float(hp[k]) * wpw[k];
        #pragma unroll
        for (int o = 16; o; o >>= 1) s += __shfl_down_sync(0xffffffffu, s, o);
        if (lane == 0) logits[d] = s + by[col];
    }
    __syncthreads();
    if (tid < 2) {
        int b = 2*cta + tid;
        float mx = -1e30f;
        for (int c = 0; c < DOUT; ++c) mx = fmaxf(mx, logits[tid*DOUT + c]);
        float e[DOUT], sum = 0.f;
        for (int c = 0; c < DOUT; ++c) { e[c] = expf(logits[tid*DOUT + c] - mx); sum += e[c]; }
        float inv = 1.f / sum;
        for (int c = 0; c < DOUT; ++c) out[b*DOUT + c] = e[c]*inv;
    }
}

extern "C" void kernel_launch(void* const* d_in, const int* in_sizes, int n_in,
                              void* d_out, int out_size) {
    const float* x   = (const float*)d_in[0];
    const float* Whx = (const float*)d_in[1];
    const float* Whh = (const float*)d_in[2];
    const float* bh  = (const float*)d_in[3];
    const float* Why = (const float*)d_in[4];
    const float* by  = (const float*)d_in[5];
    float* out = (float*)d_out;

    cudaFuncSetAttribute(rnn_hmma_kernel,
                         cudaFuncAttributeMaxDynamicSharedMemorySize, SMEM_BYTES);

    rnn_init_kernel<<<4096, 256>>>(x);
    rnn_hmma_kernel<<<GRID, NTH, SMEM_BYTES>>>(Whh, Whx, bh, Why, by, out);
}

// round 10
// speedup vs baseline: 1.1949x; 1.1949x over previous
#include <cuda_runtime.h>
#include <cuda_fp16.h>
#include <math.h>
#include <stdint.h>

// Problem constants
#define BB   256
#define TT   512
#define DIN  64
#define HH   1024
#define DOUT 10

// Config: 128 CTAs (4 batch-tiles x 32 h-tiles), tile 64 batch x 32 h-out
#define GRID 128
#define NTH  256
#define BT   64
#define HT   32
#define KCH  64
#define NCH  17            // 16 h-chunks + 1 x-chunk
#define NIB  4             // independent barrier groups (one per batch-tile)
#define IBW  32            // CTAs per ib-group

// SMEM layout (bytes). Strides padded so 8-row ldmatrix groups hit distinct banks.
#define BSTRIDE_H 1096                     // halves per Whh row (1024 + 64 Whx + 8 pad)
#define BSTRIDE_B (BSTRIDE_H*2)            // 2192 B = 548 words == 4 mod 32
#define ASTRIDE_H 72                       // halves per A row (64 + 8 pad)
#define ASTRIDE_B (ASTRIDE_H*2)            // 144 B
#define ABUF_B    (BT*ASTRIDE_B)           // 9216 B per chunk buffer
#define SM_B      0
#define SM_B_SZ   (HT*BSTRIDE_B)           // 70144
#define SM_A      SM_B_SZ
#define SM_A_SZ   (NCH*ABUF_B)             // 156672
#define SM_BIAS   (SM_A + SM_A_SZ)         // 226816
#define SMEM_BYTES (SM_BIAS + 128)         // 226944  (< 232448 cap)

#define SPIN_BOUND (1u<<20)

// Global scratch (__device__ globals: allocation-free rule)
__device__ __align__(256) __half g_h[2][BB][HH];    // double-buffered hidden state fp16
__device__ __align__(256) __half g_x[TT][BB][DIN];  // x pre-converted fp16, [t][b][d]
__device__ unsigned g_bar[TT][NIB];                 // per-step, per-ib-group barrier counters

// ---------------- helpers ----------------
__device__ __forceinline__ void cp_async16(void* sptr, const void* gptr) {
    uint32_t s = (uint32_t)__cvta_generic_to_shared(sptr);
    asm volatile("cp.async.cg.shared.global [%0], [%1], 16;" :: "r"(s), "l"(gptr));
}
__device__ __forceinline__ void cp_commit() { asm volatile("cp.async.commit_group;"); }
template<int N> __device__ __forceinline__ void cp_wait() {
    asm volatile("cp.async.wait_group %0;" :: "n"(N));
}
// switch folds to the right immediate under full unroll
__device__ __forceinline__ void cp_wait_dyn(int n) {
    switch (n) {
    case 0:  cp_wait<0>();  break;  case 1:  cp_wait<1>();  break;
    case 2:  cp_wait<2>();  break;  case 3:  cp_wait<3>();  break;
    case 4:  cp_wait<4>();  break;  case 5:  cp_wait<5>();  break;
    case 6:  cp_wait<6>();  break;  case 7:  cp_wait<7>();  break;
    case 8:  cp_wait<8>();  break;  case 9:  cp_wait<9>();  break;
    case 10: cp_wait<10>(); break;  case 11: cp_wait<11>(); break;
    case 12: cp_wait<12>(); break;  case 13: cp_wait<13>(); break;
    case 14: cp_wait<14>(); break;  case 15: cp_wait<15>(); break;
    default: cp_wait<16>(); break;
    }
}

__device__ __forceinline__ void ldsm_x4(uint32_t& r0, uint32_t& r1, uint32_t& r2, uint32_t& r3,
                                        uint32_t addr) {
    asm volatile("ldmatrix.sync.aligned.m8n8.x4.shared.b16 {%0,%1,%2,%3}, [%4];"
                 : "=r"(r0), "=r"(r1), "=r"(r2), "=r"(r3) : "r"(addr));
}

__device__ __forceinline__ void mma16816(float* c, const uint32_t* a, uint32_t b0, uint32_t b1) {
    asm volatile(
        "mma.sync.aligned.m16n8k16.row.col.f32.f16.f16.f32 "
        "{%0,%1,%2,%3}, {%4,%5,%6,%7}, {%8,%9}, {%0,%1,%2,%3};"
        : "+f"(c[0]), "+f"(c[1]), "+f"(c[2]), "+f"(c[3])
        : "r"(a[0]), "r"(a[1]), "r"(a[2]), "r"(a[3]), "r"(b0), "r"(b1));
}

__device__ __forceinline__ float tanh_fast(float x) {
    float e = __expf(2.0f * x);
    return 1.0f - __fdividef(2.0f, e + 1.0f);
}

// ---------------- init: zero state, convert x fp32->fp16 into [t][b][d] ----------------
__global__ void rnn_init_kernel(const float* __restrict__ x) {
    int i = blockIdx.x * blockDim.x + threadIdx.x;
    int stride = gridDim.x * blockDim.x;
    if (i < BB*HH) ((__half*)g_h)[i] = __ushort_as_half((unsigned short)0);
    if (i < TT*NIB) ((unsigned*)g_bar)[i] = 0u;
    for (int j = i; j < BB*TT*DIN; j += stride) {
        int d = j & 63;
        int t = (j >> 6) & 511;
        int b = j >> 15;
        g_x[t][b][d] = __float2half_rn(x[j]);
    }
}

// ---------------- persistent RNN kernel ----------------
__global__ void __launch_bounds__(NTH, 1)
rnn_hmma_kernel(const float* __restrict__ Whh, const float* __restrict__ Whx,
                const float* __restrict__ bh,  const float* __restrict__ Why,
                const float* __restrict__ by,  float* __restrict__ out)
{
    extern __shared__ char sm[];
    const uint32_t smb = (uint32_t)__cvta_generic_to_shared(sm);
    const int tid = threadIdx.x, warp = tid >> 5, lane = tid & 31;
    const int cta = blockIdx.x;
    const int jb = cta & 31, ib = cta >> 5;    // 32 h-tiles x 4 b-tiles
    const int h_base = jb * HT;
    const int b_base = ib * BT;

    // ---- stage B once: Whh [32,1024] + Whx [32,64] as fp16 rows of stride 1096 ----
    __half* bs = (__half*)(sm + SM_B);
    for (int i = tid; i < HT*HH/2; i += NTH) {
        int n = i >> 9, k = (i & 511) * 2;
        const float* src = &Whh[(size_t)(h_base + n)*HH + k];
        *(__half2*)&bs[n*BSTRIDE_H + k] = __floats2half2_rn(src[0], src[1]);
    }
    for (int i = tid; i < HT*DIN/2; i += NTH) {
        int n = i >> 5, k = (i & 31) * 2;
        *(__half2*)&bs[n*BSTRIDE_H + 1024 + k] =
            __floats2half2_rn(Whx[(h_base + n)*DIN + k], Whx[(h_base + n)*DIN + k + 1]);
    }
    float* bias_s = (float*)(sm + SM_BIAS);
    if (tid < HT) bias_s[tid] = bh[h_base + tid];
    __syncthreads();

    // warp tiling: 4 m-warps (16 rows each) x 2 n-warps (16 cols each)
    const int wp   = warp >> 1;       // pair id 0..3 (m-tile)
    const int wm   = wp * 16;
    const int wn   = (warp & 1) * 16;
    const int grp  = lane >> 2, thr4 = lane & 3;
    const int ptid = tid & 63;        // thread id within the 64-thread pair

    // ldmatrix lane address components
    const int a_row  = wm + (lane & 7) + 8*((lane >> 3) & 1);
    const int a_koff = 8 * (lane >> 4);
    const int b_row  = wn + (lane & 7) + 8*(lane >> 4);
    const int b_koff = 8 * ((lane >> 3) & 1);
    const uint32_t a_lane = smb + SM_A + a_row*ASTRIDE_B + a_koff*2;
    const uint32_t b_lane = smb + SM_B + b_row*BSTRIDE_B + b_koff*2;

    // staging assignment: thread handles rows (sr, sr+8) of pair tile, 16B unit sq
    const int sr = wm + (ptid >> 3);
    const int sq = ptid & 7;
    char* const sa0 = sm + SM_A + sr*ASTRIDE_B + sq*16;
    char* const sa1 = sm + SM_A + (sr+8)*ASTRIDE_B + sq*16;

    bool alive = true;

    for (int t = 0; t < TT; ++t) {
        const __half* hsrc = &g_h[t & 1][0][0];

        // ---- stage x chunk (h-independent) BEFORE waiting on the barrier ----
        {
            const __half* s0 = &g_x[t][b_base + sr][sq*8];
            cp_async16(sa0 + 16*ABUF_B, s0);
            cp_async16(sa1 + 16*ABUF_B, s0 + 8*DIN);
            cp_commit();
        }

        // ---- wait for h_t ready: only the 32 CTAs of our ib-group matter ----
        if (t > 0) {
            if (tid == 0 && alive) {
                unsigned spins = 0;
                while (*((volatile unsigned*)&g_bar[t-1][ib]) < IBW) {
                    if (++spins >= SPIN_BOUND) { alive = false; break; }
                    __nanosleep(8);
                }
            }
            __threadfence();
            __syncthreads();
        }

        // ---- stage h chunks 0..15 (one group each) ----
        {
            const __half* h0 = hsrc + (size_t)(b_base + sr)*HH + sq*8;
            const __half* h1 = hsrc + (size_t)(b_base + sr + 8)*HH + sq*8;
            #pragma unroll
            for (int c = 0; c < 16; ++c) {
                cp_async16(sa0 + c*ABUF_B, h0 + c*KCH);
                cp_async16(sa1 + c*ABUF_B, h1 + c*KCH);
                cp_commit();
            }
        }

        // split accumulators: even kk -> A set, odd kk -> B set (breaks mma dep chain)
        float acc0a[4] = {0.f,0.f,0.f,0.f}, acc0b[4] = {0.f,0.f,0.f,0.f};
        float acc1a[4] = {0.f,0.f,0.f,0.f}, acc1b[4] = {0.f,0.f,0.f,0.f};

        auto do_chunk = [&](int c) {
            const uint32_t abase = a_lane + c * ABUF_B;
            const uint32_t bbase = b_lane + c * (KCH * 2);
            #pragma unroll
            for (int kk = 0; kk < 4; ++kk) {
                uint32_t a0,a1,a2,a3, b0,b1,b2,b3;
                ldsm_x4(a0,a1,a2,a3, abase + kk*32);
                ldsm_x4(b0,b1,b2,b3, bbase + kk*32);
                uint32_t a[4] = {a0,a1,a2,a3};
                if (kk & 1) { mma16816(acc0b, a, b0, b1); mma16816(acc1b, a, b2, b3); }
                else        { mma16816(acc0a, a, b0, b1); mma16816(acc1a, a, b2, b3); }
            }
        };

        // ---- compute: x chunk first (already landed), then h chunks as they land ----
        cp_wait<16>();
        asm volatile("bar.sync %0, 64;" :: "r"(wp + 1) : "memory");
        do_chunk(16);
        #pragma unroll
        for (int c = 0; c < 16; ++c) {
            cp_wait_dyn(15 - c);
            asm volatile("bar.sync %0, 64;" :: "r"(wp + 1) : "memory");
            do_chunk(c);
        }

        // ---- epilogue: combine accs, bias + tanh, store h_new fp16 ----
        {
            __half* hdst = &g_h[(t + 1) & 1][0][0];
            const int r0 = b_base + wm + grp;
            #pragma unroll
            for (int tile = 0; tile < 2; ++tile) {
                const float* aa = tile ? acc1a : acc0a;
                const float* ab = tile ? acc1b : acc0b;
                const int col = h_base + wn + tile*8 + 2*thr4;
                float bl  = bias_s[wn + tile*8 + 2*thr4];
                float bhp = bias_s[wn + tile*8 + 2*thr4 + 1];
                __half2 v0 = __floats2half2_rn(tanh_fast(aa[0] + ab[0] + bl),
                                               tanh_fast(aa[1] + ab[1] + bhp));
                __half2 v1 = __floats2half2_rn(tanh_fast(aa[2] + ab[2] + bl),
                                               tanh_fast(aa[3] + ab[3] + bhp));
                *(__half2*)&hdst[(size_t)r0*HH + col]     = v0;
                *(__half2*)&hdst[(size_t)(r0+8)*HH + col] = v1;
            }
        }

        // ---- arrive at our ib-group barrier (wait happens next iteration) ----
        __threadfence();
        __syncthreads();
        if (tid == 0) atomicAdd(&g_bar[t][ib], 1u);
    }

    // ---- wait for final h of the ib-group that owns our output rows ----
    {
        const int ib_read = (2*cta) >> 6;
        if (tid == 0 && alive) {
            unsigned spins = 0;
            while (*((volatile unsigned*)&g_bar[TT-1][ib_read]) < IBW) {
                if (++spins >= SPIN_BOUND) { alive = false; break; }
                __nanosleep(8);
            }
        }
        __threadfence();
        __syncthreads();
    }

    // ---- output: o = h_final @ Why^T + by, softmax over 10 (2 batch rows per CTA) ----
    float* logits = (float*)(sm + SM_A);   // 20 floats; mainloop smem dead now
    const __half* hf = &g_h[0][0][0];      // TT even -> final h in buffer 0
    for (int d = warp; d < 2*DOUT; d += 8) {
        int row = d / DOUT, col = d % DOUT;
        int b = 2*cta + row;
        const __half* hp = hf + (size_t)b*HH;
        const float* wpw = Why + (size_t)col*HH;
        float s = 0.f;
        for (int k = lane; k < HH; k += 32)
            s += __half2float(hp[k]) * wpw[k];
        #pragma unroll
        for (int o = 16; o; o >>= 1) s += __shfl_down_sync(0xffffffffu, s, o);
        if (lane == 0) logits[d] = s + by[col];
    }
    __syncthreads();
    if (tid < 2) {
        int b = 2*cta + tid;
        float mx = -1e30f;
        for (int c = 0; c < DOUT; ++c) mx = fmaxf(mx, logits[tid*DOUT + c]);
        float e[DOUT], sum = 0.f;
        for (int c = 0; c < DOUT; ++c) { e[c] = expf(logits[tid*DOUT + c] - mx); sum += e[c]; }
        float inv = 1.f / sum;
        for (int c = 0; c < DOUT; ++c) out[b*DOUT + c] = e[c]*inv;
    }
}

extern "C" void kernel_launch(void* const* d_in, const int* in_sizes, int n_in,
                              void* d_out, int out_size) {
    const float* x   = (const float*)d_in[0];
    const float* Whx = (const float*)d_in[1];
    const float* Whh = (const float*)d_in[2];
    const float* bh  = (const float*)d_in[3];
    const float* Why = (const float*)d_in[4];
    const float* by  = (const float*)d_in[5];
    float* out = (float*)d_out;

    cudaFuncSetAttribute(rnn_hmma_kernel,
                         cudaFuncAttributeMaxDynamicSharedMemorySize, SMEM_BYTES);

    rnn_init_kernel<<<4096, 256>>>(x);
    rnn_hmma_kernel<<<GRID, NTH, SMEM_BYTES>>>(Whh, Whx, bh, Why, by, out);
}